// round 4
// baseline (speedup 1.0000x reference)
#include <cuda_runtime.h>

#define NMAX 1048576
#define HMAX (1 << 19)          // 524288 hash slots (actual H ~ 128000)
#define SCAN_THREADS 256
#define SCAN_ELEMS 4
#define SCAN_CHUNK (SCAN_THREADS * SCAN_ELEMS)   // 1024
#define SCAN_BLOCKS (HMAX / SCAN_CHUNK)          // 512
#define PREP_BLOCKS 2048
#define PREP_THREADS 256

// XLA rewrites divide-by-const into multiply-by-reciprocal; 1/0.05f rounds to 20.0f exactly.
#define INV_SIZE 20.0f

__device__ __align__(16) int g_count[HMAX];
__device__ __align__(16) int g_cursor[HMAX];
__device__ int g_occ[HMAX];      // g_occ[rank] = slot (compacted occupied slots)
__device__ int g_hash[NMAX];
__device__ int g_sorted[NMAX];
__device__ __align__(16) unsigned long long g_bsum[SCAN_BLOCKS];
__device__ unsigned int g_bmm[PREP_BLOCKS * 6];
__device__ int g_ctr0;           // self-resetting ticket counters (start at 0)
__device__ int g_ctr1;
__device__ int g_K;              // number of occupied clusters

struct Params { float s0, s1, s2; int d0, d01, d012; int b0; };
__device__ Params g_par;

// order-preserving float<->uint encoding for min/max
__device__ __forceinline__ unsigned fenc(float f) {
    unsigned u = __float_as_uint(f);
    return (u & 0x80000000u) ? ~u : (u | 0x80000000u);
}
__device__ __forceinline__ float fdec(unsigned v) {
    return __uint_as_float((v & 0x80000000u) ? (v ^ 0x80000000u) : ~v);
}

// streaming zero of float4 range [a,b)
__device__ __forceinline__ void zero_range(float4* o4, long long a, long long b,
                                           long long tid, long long nth) {
    float4 z = make_float4(0.f, 0.f, 0.f, 0.f);
    for (long long t = a + tid; t < b; t += nth) __stcs(&o4[t], z);
}

// warp-inclusive scan on u64
__device__ __forceinline__ unsigned long long wscan(unsigned long long v, int lane) {
    #pragma unroll
    for (int off = 1; off < 32; off <<= 1) {
        unsigned long long u = __shfl_up_sync(0xffffffffu, v, off);
        if (lane >= off) v += u;
    }
    return v;
}
__device__ __forceinline__ unsigned long long wreduce(unsigned long long v) {
    #pragma unroll
    for (int off = 16; off > 0; off >>= 1)
        v += __shfl_down_sync(0xffffffffu, v, off);
    return v;
}

// ---------------- fused init + minmax + params ----------------
__global__ void k_prep(const float* __restrict__ pos, const int* __restrict__ batch,
                       float4* o4, float* out, long long out_n, int n,
                       long long za, long long zb) {
    long long tid = (long long)blockIdx.x * blockDim.x + threadIdx.x;
    long long nth = (long long)gridDim.x * blockDim.x;

    // zero histogram
    for (long long t = tid; t < HMAX / 4; t += nth)
        ((int4*)g_count)[t] = make_int4(0, 0, 0, 0);
    // zero output share (+ scalar tail of whole output)
    zero_range(o4, za, zb, tid, nth);
    for (long long t = (out_n & ~3LL) + tid; t < out_n; t += nth) out[t] = 0.f;

    // per-thread minmax over points
    unsigned lmin[3] = {~0u, ~0u, ~0u}, lmax[3] = {0u, 0u, 0u};
    for (long long i = tid; i < n; i += nth) {
        #pragma unroll
        for (int d = 0; d < 3; d++) {
            unsigned e = fenc(pos[3 * i + d]);
            lmin[d] = min(lmin[d], e);
            lmax[d] = max(lmax[d], e);
        }
    }
    __shared__ unsigned smin[3], smax[3];
    if (threadIdx.x == 0) {
        smin[0] = smin[1] = smin[2] = ~0u;
        smax[0] = smax[1] = smax[2] = 0u;
    }
    __syncthreads();
    #pragma unroll
    for (int d = 0; d < 3; d++) { atomicMin(&smin[d], lmin[d]); atomicMax(&smax[d], lmax[d]); }
    __syncthreads();
    if (threadIdx.x < 3) {
        g_bmm[blockIdx.x * 6 + threadIdx.x] = smin[threadIdx.x];
        g_bmm[blockIdx.x * 6 + 3 + threadIdx.x] = smax[threadIdx.x];
    }
    __threadfence();
    __shared__ int isLast;
    if (threadIdx.x == 0)
        isLast = (atomicAdd(&g_ctr0, 1) == (int)gridDim.x - 1);
    __syncthreads();
    if (!isLast) return;

    // last block: reduce all block partials, compute params
    unsigned rmin[3] = {~0u, ~0u, ~0u}, rmax[3] = {0u, 0u, 0u};
    for (int b = threadIdx.x; b < PREP_BLOCKS; b += blockDim.x) {
        #pragma unroll
        for (int d = 0; d < 3; d++) {
            rmin[d] = min(rmin[d], g_bmm[b * 6 + d]);
            rmax[d] = max(rmax[d], g_bmm[b * 6 + 3 + d]);
        }
    }
    __syncthreads();
    if (threadIdx.x == 0) {
        smin[0] = smin[1] = smin[2] = ~0u;
        smax[0] = smax[1] = smax[2] = 0u;
    }
    __syncthreads();
    #pragma unroll
    for (int d = 0; d < 3; d++) { atomicMin(&smin[d], rmin[d]); atomicMax(&smax[d], rmax[d]); }
    __syncthreads();
    if (threadIdx.x == 0) {
        int dims[3];
        float s[3];
        #pragma unroll
        for (int d = 0; d < 3; d++) {
            s[d] = fdec(smin[d]);
            float e = fdec(smax[d]);
            dims[d] = (int)(floorf(__fmul_rn(__fsub_rn(e, s[d]), INV_SIZE)) + 1.0f);
        }
        Params p;
        p.s0 = s[0]; p.s1 = s[1]; p.s2 = s[2];
        p.d0 = dims[0];
        p.d01 = dims[0] * dims[1];
        p.d012 = dims[0] * dims[1] * dims[2];
        p.b0 = batch[0];
        g_par = p;
        g_ctr0 = 0;   // reset for next replay
    }
}

// ---------------- hash + histogram (+ zero share) ----------------
__global__ void k_hash(const float* __restrict__ pos, const int* __restrict__ batch, int n,
                       float4* o4, long long za, long long zb) {
    long long tid = (long long)blockIdx.x * blockDim.x + threadIdx.x;
    long long nth = (long long)gridDim.x * blockDim.x;
    zero_range(o4, za, zb, tid, nth);
    int i = (int)tid;
    if (i >= n) return;
    Params p = g_par;
    float p0 = pos[3 * i + 0], p1 = pos[3 * i + 1], p2 = pos[3 * i + 2];
    int c0 = (int)floorf(__fmul_rn(__fsub_rn(p0, p.s0), INV_SIZE));
    int c1 = (int)floorf(__fmul_rn(__fsub_rn(p1, p.s1), INV_SIZE));
    int c2 = (int)floorf(__fmul_rn(__fsub_rn(p2, p.s2), INV_SIZE));
    int cb = batch[i] - p.b0;
    int h = c0 + c1 * p.d0 + c2 * p.d01 + cb * p.d012;
    g_hash[i] = h;
    atomicAdd(&g_count[h], 1);
}

// ---------------- scan pass 1: block sums (shuffle reduce) + fused pass 2 ----------------
__global__ void k_scan1(float4* o4, long long za, long long zb) {
    long long tid = (long long)blockIdx.x * blockDim.x + threadIdx.x;
    long long nth = (long long)gridDim.x * blockDim.x;
    zero_range(o4, za, zb, tid, nth);

    int t = threadIdx.x;
    int lane = t & 31, wid = t >> 5;
    int4 cv = ((const int4*)g_count)[blockIdx.x * SCAN_THREADS + t];
    unsigned long long s =
        (unsigned long long)(unsigned)(cv.x + cv.y + cv.z + cv.w) |
        ((unsigned long long)((cv.x > 0) + (cv.y > 0) + (cv.z > 0) + (cv.w > 0)) << 32);
    s = wreduce(s);
    __shared__ unsigned long long wsum[8];
    if (lane == 0) wsum[wid] = s;
    __syncthreads();
    if (t == 0) {
        unsigned long long tot = 0;
        #pragma unroll
        for (int j = 0; j < 8; j++) tot += wsum[j];
        g_bsum[blockIdx.x] = tot;
    }
    __threadfence();
    __shared__ int isLast;
    if (t == 0) isLast = (atomicAdd(&g_ctr1, 1) == (int)gridDim.x - 1);
    __syncthreads();
    if (!isLast) return;

    // exclusive scan of SCAN_BLOCKS (512) block sums: thread t owns 2 values
    unsigned long long a = g_bsum[2 * t], b = g_bsum[2 * t + 1];
    unsigned long long run = a + b;
    unsigned long long inc = wscan(run, lane);
    __shared__ unsigned long long wagg[8];
    if (lane == 31) wagg[wid] = inc;
    __syncthreads();
    unsigned long long woff = 0;
    #pragma unroll
    for (int j = 0; j < 8; j++) {
        unsigned long long v = wagg[j];
        if (j < wid) woff += v;
    }
    unsigned long long excl = woff + inc - run;
    g_bsum[2 * t] = excl;
    g_bsum[2 * t + 1] = excl + a;
    if (t == SCAN_THREADS - 1) {
        g_K = (int)((woff + inc) >> 32);   // total occupied clusters
        g_ctr1 = 0;
    }
}

// ---------------- scan pass 3: per-element prefixes, cursor + compaction ----------------
__global__ void k_scan3(float4* o4, long long za, long long zb) {
    long long tid = (long long)blockIdx.x * blockDim.x + threadIdx.x;
    long long nth = (long long)gridDim.x * blockDim.x;
    zero_range(o4, za, zb, tid, nth);

    int t = threadIdx.x;
    int lane = t & 31, wid = t >> 5;
    int eb = blockIdx.x * SCAN_CHUNK + t * SCAN_ELEMS;
    int4 cv = *(const int4*)&g_count[eb];
    int c[4] = {cv.x, cv.y, cv.z, cv.w};
    unsigned long long loc[4];
    unsigned long long run = 0;
    #pragma unroll
    for (int j = 0; j < SCAN_ELEMS; j++) {
        loc[j] = run;
        run += (unsigned long long)c[j] | ((unsigned long long)(c[j] > 0) << 32);
    }
    unsigned long long inc = wscan(run, lane);
    __shared__ unsigned long long wagg[8];
    if (lane == 31) wagg[wid] = inc;
    __syncthreads();
    unsigned long long woff = 0;
    #pragma unroll
    for (int j = 0; j < 8; j++) {
        unsigned long long v = wagg[j];
        if (j < wid) woff += v;
    }
    unsigned long long pre = g_bsum[blockIdx.x] + woff + (inc - run);
    #pragma unroll
    for (int j = 0; j < SCAN_ELEMS; j++) {
        unsigned long long v = pre + loc[j];
        g_cursor[eb + j] = (int)(v & 0xFFFFFFFFull);
        if (c[j] > 0) g_occ[(int)(v >> 32)] = eb + j;
    }
}

// ---------------- scatter (counting sort) (+ zero share) ----------------
__global__ void k_scatter(int n, float4* o4, long long za, long long zb) {
    long long tid = (long long)blockIdx.x * blockDim.x + threadIdx.x;
    long long nth = (long long)gridDim.x * blockDim.x;
    zero_range(o4, za, zb, tid, nth);
    int i = (int)tid;
    if (i >= n) return;
    int h = g_hash[i];
    int p = atomicAdd(&g_cursor[h], 1);
    g_sorted[p] = i;
}

// ---------------- gather: persistent, one warp per occupied cluster ----------------
__global__ void k_gather(const float* __restrict__ x, const float* __restrict__ pos,
                         float* __restrict__ out, int n) {
    int lane = threadIdx.x & 31;
    int warp0 = (blockIdx.x * blockDim.x + threadIdx.x) >> 5;
    int nwarps = (gridDim.x * blockDim.x) >> 5;
    int K = g_K;
    Params pr = g_par;
    const float2* x2 = (const float2*)x;
    const float NEG_INF = __int_as_float(0xff800000);

    for (int w = warp0; w < K; w += nwarps) {
        int slot = g_occ[w];
        int cnt = g_count[slot];
        int end = g_cursor[slot];   // after scatter bump: beg + cnt
        int beg = end - cnt;

        float2 vmax = make_float2(NEG_INF, NEG_INF);
        float psum = 0.f;
        for (int b = 0; b < cnt; b += 32) {
            int m = min(cnt - b, 32);
            int idxl = (lane < m) ? g_sorted[beg + b + lane] : 0;
            #pragma unroll 8
            for (int j = 0; j < m; j++) {
                int idx = __shfl_sync(0xffffffffu, idxl, j);
                float2 v = __ldcs(&x2[(size_t)idx * 32 + lane]);
                vmax.x = fmaxf(vmax.x, v.x);
                vmax.y = fmaxf(vmax.y, v.y);
                if (lane < 3) psum += __ldg(&pos[(size_t)idx * 3 + lane]);
            }
        }
        __stcs(&((float2*)out)[(size_t)w * 32 + lane], vmax);
        if (lane < 3)
            out[(size_t)n * 64 + (size_t)w * 3 + lane] = __fdiv_rn(psum, (float)cnt);
        if (lane == 3)
            out[(size_t)n * 67 + w] = (float)(slot / pr.d012 + pr.b0);
    }
}

// ---------------- launch ----------------
extern "C" void kernel_launch(void* const* d_in, const int* in_sizes, int n_in,
                              void* d_out, int out_size) {
    const float* x = (const float*)d_in[0];
    const float* pos = (const float*)d_in[1];
    const int* batch = (const int*)d_in[2];
    int n = in_sizes[2];
    if (n > NMAX) n = NMAX;
    float* out = (float*)d_out;
    float4* o4 = (float4*)d_out;
    long long Q = (long long)out_size >> 2;

    // zero-work shares across latency-bound kernels
    long long q1 = (long long)(Q * 50 / 100);
    long long q2 = (long long)(Q * 72 / 100);
    long long q3 = (long long)(Q * 80 / 100);
    long long q4 = (long long)(Q * 88 / 100);

    int nb = (n + 255) / 256;
    k_prep<<<PREP_BLOCKS, PREP_THREADS>>>(pos, batch, o4, out, (long long)out_size, n, 0, q1);
    k_hash<<<nb, 256>>>(pos, batch, n, o4, q1, q2);
    k_scan1<<<SCAN_BLOCKS, SCAN_THREADS>>>(o4, q2, q3);
    k_scan3<<<SCAN_BLOCKS, SCAN_THREADS>>>(o4, q3, q4);
    k_scatter<<<nb, 256>>>(n, o4, q4, Q);
    k_gather<<<1184, 256>>>(x, pos, out, n);
}